// round 14
// baseline (speedup 1.0000x reference)
#include <cuda_runtime.h>
#include <cuda_bf16.h>
#include <cstdint>

typedef __nv_bfloat16 bf16;
typedef unsigned long long u64;

#define NN 128
#define PP 256
#define DD 128
#define HD 16
#define ROWS (NN*PP)      // 32768
#define HIDDEN 2048

// ---------------- scratch (device globals; no cudaMalloc allowed) ----------
__device__ bf16  g_xhi[(size_t)ROWS * DD],    g_xlo[(size_t)ROWS * DD];
__device__ float g_y1 [(size_t)ROWS * 768];
__device__ bf16  g_thi[(size_t)ROWS * 256],   g_tlo[(size_t)ROWS * 256];
__device__ float g_y2 [(size_t)ROWS * 768];
__device__ bf16  g_pahi[(size_t)ROWS * 256],  g_palo[(size_t)ROWS * 256];
// transposed split weights: Bt[n][k]
__device__ bf16  g_w1t_hi[768 * 128],   g_w1t_lo[768 * 128];
__device__ bf16  g_w2t_hi[768 * 256],   g_w2t_lo[768 * 256];
__device__ bf16  g_f2t_hi[256 * 2048],  g_f2t_lo[256 * 2048];   // fc2_w^T split
__device__ bf16  g_f1a_hi[256 * 2048],  g_f1a_lo[256 * 2048];   // fc1_w row-major split
// fused FC weight: W12T = fc2_w^T @ fc1_w^T (split-K partials, then split)
__device__ float g_w12p[8 * 256 * 256];
__device__ bf16  g_w12h[256 * 256],     g_w12l[256 * 256];
__device__ float g_b12[256];

// ---------------- helpers ---------------------------------------------------
__device__ __forceinline__ uint32_t smem_u32(const void* p) {
    uint32_t a;
    asm("{ .reg .u64 t; cvta.to.shared.u64 t, %1; cvt.u32.u64 %0, t; }"
        : "=r"(a) : "l"(p));
    return a;
}
__device__ __forceinline__ void cp16(uint32_t dst, const void* src) {
    asm volatile("cp.async.cg.shared.global [%0], [%1], 16;"
                 :: "r"(dst), "l"(src) : "memory");
}
__device__ __forceinline__ void mma_bf16(float* d, const uint32_t* a, const uint32_t* b) {
    asm volatile(
        "mma.sync.aligned.m16n8k16.row.col.f32.bf16.bf16.f32 "
        "{%0,%1,%2,%3}, {%4,%5,%6,%7}, {%8,%9}, {%0,%1,%2,%3};"
        : "+f"(d[0]), "+f"(d[1]), "+f"(d[2]), "+f"(d[3])
        : "r"(a[0]), "r"(a[1]), "r"(a[2]), "r"(a[3]), "r"(b[0]), "r"(b[1]));
}
__device__ __forceinline__ void ldsm4(uint32_t& r0, uint32_t& r1, uint32_t& r2,
                                      uint32_t& r3, uint32_t addr) {
    asm volatile("ldmatrix.sync.aligned.m8n8.x4.shared.b16 {%0,%1,%2,%3}, [%4];"
                 : "=r"(r0), "=r"(r1), "=r"(r2), "=r"(r3) : "r"(addr));
}
__device__ __forceinline__ void split1(float v, uint32_t& hb, uint32_t& lb) {
    bf16 h = __float2bfloat16(v);
    bf16 l = __float2bfloat16(v - __bfloat162float(h));
    hb = (uint32_t)__bfloat16_as_ushort(h);
    lb = (uint32_t)__bfloat16_as_ushort(l);
}
// pack two f32 into bf16x2 (even value -> low half)
__device__ __forceinline__ uint32_t packbf(float even, float odd) {
    uint32_t r;
    asm("cvt.rn.bf16x2.f32 %0, %1, %2;" : "=r"(r) : "f"(odd), "f"(even));
    return r;
}
// split pair (even,odd) into hi/lo bf16x2 regs
__device__ __forceinline__ void splitpair(float e, float o, uint32_t& h, uint32_t& l) {
    h = packbf(e, o);
    const float he = __uint_as_float(h << 16);
    const float ho = __uint_as_float(h & 0xffff0000u);
    l = packbf(e - he, o - ho);
}

// ---------------- split-bf16 mma.sync GEMM ---------------------------------
#define TM 128
#define TN 128
#define KC 32
#define ROWB 64
#define OPB (128 * ROWB)
#define STB (4 * OPB)
#define NSTG 3
#define SMEM_BYTES (NSTG * STB)      // 98304

template <int EPI>
__global__ __launch_bounds__(256, 2) void gemm_mma(
    const bf16* __restrict__ Ahi, const bf16* __restrict__ Alo,
    const bf16* __restrict__ Bhi, const bf16* __restrict__ Blo,
    float* __restrict__ C, bf16* __restrict__ Chi, bf16* __restrict__ Clo,
    const float* __restrict__ bias, int K, int ldc, int lda)
{
    extern __shared__ char smem[];
    const uint32_t sb = smem_u32(smem);
    const int tid = threadIdx.x, lane = tid & 31, wid = tid >> 5;
    const int wm = wid >> 2, wn = wid & 3;
    const int bn = blockIdx.x * TN, bm = blockIdx.y * TM;
    const int lr = lane >> 2, lc = lane & 3;
    const int koff = (EPI == 2) ? (int)blockIdx.z * K : 0;

    const int j  = lane >> 3;
    const int rr = ((j & 1) << 3) + (lane & 7);
    const int xr = (rr >> 1) & 3;
    const int cj = j >> 1;
    uint32_t loff[2];
    loff[0] = (uint32_t)(rr * ROWB + (((0 + cj) ^ xr) << 4));
    loff[1] = (uint32_t)(rr * ROWB + (((2 + cj) ^ xr) << 4));

    float acc[4][4][4];
    #pragma unroll
    for (int i = 0; i < 4; i++)
        #pragma unroll
        for (int jj = 0; jj < 4; jj++)
            #pragma unroll
            for (int e = 0; e < 4; e++) acc[i][jj][e] = 0.f;

    const int nc = K / KC;

    auto load_stage = [&](int c) {
        const int buf = c % NSTG;
        const bf16* gs[4] = {
            Ahi + (size_t)bm * lda + koff + c * KC,
            Alo + (size_t)bm * lda + koff + c * KC,
            Bhi + (size_t)bn * lda + koff + c * KC,
            Blo + (size_t)bn * lda + koff + c * KC };
        #pragma unroll
        for (int op = 0; op < 4; op++) {
            #pragma unroll
            for (int l = 0; l < 2; l++) {
                const int idx = tid + l * 256;
                const int r = idx >> 2, c8 = idx & 3;
                const uint32_t dst = sb + buf * STB + op * OPB +
                    (uint32_t)(r * ROWB + ((c8 ^ ((r >> 1) & 3)) << 4));
                cp16(dst, gs[op] + (size_t)r * lda + c8 * 8);
            }
        }
        asm volatile("cp.async.commit_group;" ::: "memory");
    };

    load_stage(0);
    if (nc > 1) load_stage(1);

    for (int c = 0; c < nc; c++) {
        if (c < nc - 1) {
            asm volatile("cp.async.wait_group 1;" ::: "memory");
        } else {
            asm volatile("cp.async.wait_group 0;" ::: "memory");
        }
        __syncthreads();
        if (c + 2 < nc) load_stage(c + 2);

        const uint32_t st = sb + (c % NSTG) * STB;
        const uint32_t aB = st + (uint32_t)(wm * 64 * ROWB);
        const uint32_t bB = st + 2 * OPB + (uint32_t)(wn * 32 * ROWB);

        #pragma unroll
        for (int k16 = 0; k16 < 2; k16++) {
            const uint32_t lo = loff[k16];
            uint32_t bh[4][2], bl[4][2];
            #pragma unroll
            for (int ntp = 0; ntp < 2; ntp++) {
                const uint32_t nb = bB + (uint32_t)(ntp * 16 * ROWB) + lo;
                ldsm4(bh[2*ntp][0], bh[2*ntp+1][0], bh[2*ntp][1], bh[2*ntp+1][1], nb);
                ldsm4(bl[2*ntp][0], bl[2*ntp+1][0], bl[2*ntp][1], bl[2*ntp+1][1], nb + OPB);
            }
            uint32_t ah[2][4], al[2][4];
            ldsm4(ah[0][0], ah[0][1], ah[0][2], ah[0][3], aB + lo);
            ldsm4(al[0][0], al[0][1], al[0][2], al[0][3], aB + OPB + lo);
            #pragma unroll
            for (int mt = 0; mt < 4; mt++) {
                const int cur = mt & 1, nxt = cur ^ 1;
                if (mt < 3) {
                    const uint32_t ab = aB + (uint32_t)((mt + 1) * 16 * ROWB) + lo;
                    ldsm4(ah[nxt][0], ah[nxt][1], ah[nxt][2], ah[nxt][3], ab);
                    ldsm4(al[nxt][0], al[nxt][1], al[nxt][2], al[nxt][3], ab + OPB);
                }
                #pragma unroll
                for (int nt = 0; nt < 4; nt++) {
                    mma_bf16(acc[mt][nt], ah[cur], bh[nt]);
                    mma_bf16(acc[mt][nt], ah[cur], bl[nt]);
                    mma_bf16(acc[mt][nt], al[cur], bh[nt]);
                }
            }
        }
    }

    const size_t zoff = (EPI == 2) ? (size_t)blockIdx.z * 65536 : 0;
    #pragma unroll
    for (int mt = 0; mt < 4; mt++) {
        #pragma unroll
        for (int nt = 0; nt < 4; nt++) {
            const int row = bm + wm * 64 + mt * 16 + lr;
            const int col = bn + wn * 32 + nt * 8 + lc * 2;
            float v0 = acc[mt][nt][0], v1 = acc[mt][nt][1];
            float v2 = acc[mt][nt][2], v3 = acc[mt][nt][3];
            if (EPI == 0 && bias) {
                const float b0 = __ldg(bias + col), b1 = __ldg(bias + col + 1);
                v0 += b0; v1 += b1; v2 += b0; v3 += b1;
            }
            if (EPI != 1) {
                *(float2*)(C + zoff + (size_t)row * ldc + col)       = make_float2(v0, v1);
                *(float2*)(C + zoff + (size_t)(row + 8) * ldc + col) = make_float2(v2, v3);
            } else {
                uint32_t h0, l0, h1, l1;
                splitpair(v0, v1, h0, l0);
                splitpair(v2, v3, h1, l1);
                *(uint32_t*)(Chi + (size_t)row * ldc + col)       = h0;
                *(uint32_t*)(Chi + (size_t)(row + 8) * ldc + col) = h1;
                *(uint32_t*)(Clo + (size_t)row * ldc + col)       = l0;
                *(uint32_t*)(Clo + (size_t)(row + 8) * ldc + col) = l1;
            }
        }
    }
}

// ---------------- fused conversion kernel (ONE launch) ---------------------
__global__ __launch_bounds__(256) void conv_all(
    const float* __restrict__ x, bf16* __restrict__ xhi, bf16* __restrict__ xlo,
    const float* __restrict__ W1, const float* __restrict__ W2,
    const float* __restrict__ fc1w, const float* __restrict__ fc2w,
    const float* __restrict__ fc1b, const float* __restrict__ fc2b,
    bf16* __restrict__ w1h, bf16* __restrict__ w1l,
    bf16* __restrict__ w2h, bf16* __restrict__ w2l,
    bf16* __restrict__ f2h, bf16* __restrict__ f2l,
    bf16* __restrict__ f1ah, bf16* __restrict__ f1al,
    float* __restrict__ b12)
{
    __shared__ float tile[32][33];
    const int tid = threadIdx.x;
    int b = blockIdx.x;

    if (b < 4096) {                       // x split
        const int i = b * 256 + tid;
        float4 v = ((const float4*)x)[i];
        uint32_t h0, l0, h1, l1;
        splitpair(v.x, v.y, h0, l0);
        splitpair(v.z, v.w, h1, l1);
        ((uint2*)xhi)[i] = make_uint2(h0, h1);
        ((uint2*)xlo)[i] = make_uint2(l0, l1);
        return;
    }
    b -= 4096;

    if (b >= 800 && b < 1312) {           // fc1_w elementwise split (512)
        const int i = (b - 800) * 256 + tid;
        float4 v = ((const float4*)fc1w)[i];
        uint32_t h0, l0, h1, l1;
        splitpair(v.x, v.y, h0, l0);
        splitpair(v.z, v.w, h1, l1);
        ((uint2*)f1ah)[i] = make_uint2(h0, h1);
        ((uint2*)f1al)[i] = make_uint2(l0, l1);
        return;
    }
    if (b >= 1312) {                      // b12 (256 blocks, one n each)
        const int n = b - 1312;
        float s = 0.f;
        for (int k = tid; k < HIDDEN; k += 256)
            s += fc1b[k] * fc2w[(size_t)k * 256 + n];
        float* red = &tile[0][0];
        red[tid] = s;
        __syncthreads();
        for (int w = 128; w > 0; w >>= 1) {
            if (tid < w) red[tid] += red[tid + w];
            __syncthreads();
        }
        if (tid == 0) b12[n] = red[0] + fc2b[n];
        return;
    }

    const float* B; bf16 *Th, *Tl;
    int K, N, n_off, out_ld, bx, by;
    if (b < 96) {                          // W1 transpose-split
        const int q = b / 32, r = b % 32;
        B = W1 + (size_t)q * 128 * 256; Th = w1h; Tl = w1l;
        K = 128; N = 256; n_off = q * 256; out_ld = 128;
        bx = r % 8; by = r / 8;
    } else if (b < 288) {                  // W2 transpose-split
        b -= 96;
        const int q = b / 64, r = b % 64;
        B = W2 + (size_t)q * 256 * 256; Th = w2h; Tl = w2l;
        K = 256; N = 256; n_off = q * 256; out_ld = 256;
        bx = r % 8; by = r / 8;
    } else {                               // fc2_w transpose-split (512)
        b -= 288;
        B = fc2w; Th = f2h; Tl = f2l;
        K = 2048; N = 256; n_off = 0; out_ld = 2048;
        bx = b % 8; by = b / 8;
    }

    const int n0 = bx * 32, k0 = by * 32;
    const int tx = tid & 31, ty = tid >> 5;
    #pragma unroll
    for (int i = 0; i < 4; i++) {
        const int r = ty + i * 8;
        tile[r][tx] = B[(size_t)(k0 + r) * N + n0 + tx];
    }
    __syncthreads();
    #pragma unroll
    for (int i = 0; i < 4; i++) {
        const int n = ty + i * 8;
        const float v = tile[tx][n];
        uint32_t hb, lb;
        split1(v, hb, lb);
        const size_t o = (size_t)(n_off + n0 + n) * out_ld + k0 + tx;
        Th[o] = __ushort_as_bfloat16((unsigned short)hb);
        Tl[o] = __ushort_as_bfloat16((unsigned short)lb);
    }
}

// ---------------- W12 partial reduce + split -------------------------------
__global__ __launch_bounds__(256) void w12_reduce_split(
    const float* __restrict__ w12p, bf16* __restrict__ w12h, bf16* __restrict__ w12l)
{
    const int i = blockIdx.x * 256 + threadIdx.x;
    float4 s = ((const float4*)w12p)[i];
    #pragma unroll
    for (int z = 1; z < 8; z++) {
        float4 p = ((const float4*)w12p)[z * 16384 + i];
        s.x += p.x; s.y += p.y; s.z += p.z; s.w += p.w;
    }
    uint32_t h0, l0, h1, l1;
    splitpair(s.x, s.y, h0, l0);
    splitpair(s.z, s.w, h1, l1);
    ((uint2*)w12h)[i] = make_uint2(h0, h1);
    ((uint2*)w12l)[i] = make_uint2(l0, l1);
}

// ---------------- MMA flash attention (no-max streaming softmax) -----------
// Register-staged K/V prefetch: LDG at top of tile loop (hidden under mma),
// split+STS after compute. V staged transposed with 2 threads/key.
template <int SEQ, int TEMP>
__global__ __launch_bounds__(256) void attn_mma(
    const float* __restrict__ y, bf16* __restrict__ oH, bf16* __restrict__ oL)
{
    constexpr int QW = SEQ / 8;
    constexpr int MT = QW / 16;
    constexpr int QROW = 48;
    constexpr int VROW = 144;
    constexpr int KHI = 64 * QROW;
    constexpr int VHI = 16 * VROW;
    constexpr int KVSTR = 2 * KHI + 2 * VHI;
    constexpr int QB = 2 * SEQ * QROW;
    constexpr int NTILES = SEQ / 64;

    __shared__ char sm[QB + 2 * KVSTR];

    const int bx = blockIdx.x, a = blockIdx.y;
    const int tid = threadIdx.x, lane = tid & 31, w = tid >> 5;
    const uint32_t sb = smem_u32(sm);

    const int j  = lane >> 3;
    const int rr = ((j & 1) << 3) + (lane & 7);
    const int cj = j >> 1;
    const uint32_t qoff = (uint32_t)(rr * QROW + cj * 16);
    const uint32_t voffl = (uint32_t)(rr * VROW + cj * 16);

    auto rowof = [&](int idx) -> size_t {
        return TEMP ? ((size_t)idx * 256 + bx) : ((size_t)bx * 256 + idx);
    };

    // ---- stage Q (once) ----
    if (tid < SEQ) {
        const float* p = y + rowof(tid) * 768 + a * 16;
        uint32_t h[8], l[8];
        #pragma unroll
        for (int c = 0; c < 8; c++) {
            float2 v = *(const float2*)(p + c * 2);
            splitpair(v.x, v.y, h[c], l[c]);
        }
        *(uint4*)(sm + tid * QROW)      = make_uint4(h[0], h[1], h[2], h[3]);
        *(uint4*)(sm + tid * QROW + 16) = make_uint4(h[4], h[5], h[6], h[7]);
        char* ql = sm + SEQ * QROW;
        *(uint4*)(ql + tid * QROW)      = make_uint4(l[0], l[1], l[2], l[3]);
        *(uint4*)(ql + tid * QROW + 16) = make_uint4(l[4], l[5], l[6], l[7]);
    }

    // register staging buffers
    float2 kr[8];
    float  vr[8];

    auto stage_load = [&](int kt) {
        if (tid < 64) {                    // K row tid
            const float* p = y + rowof(kt * 64 + tid) * 768 + a * 16 + 256;
            #pragma unroll
            for (int c = 0; c < 8; c++) kr[c] = ((const float2*)p)[c];
        } else if (tid < 192) {            // V: 2 threads per key
            const int key = (tid - 64) >> 1;
            const int dh  = ((tid - 64) & 1) * 8;
            const float* p = y + rowof(kt * 64 + key) * 768 + a * 16 + 512 + dh;
            #pragma unroll
            for (int d = 0; d < 8; d++) vr[d] = p[d];
        }
    };
    auto stage_store = [&](int buf) {
        char* base = sm + QB + buf * KVSTR;
        if (tid < 64) {
            uint32_t h[8], l[8];
            #pragma unroll
            for (int c = 0; c < 8; c++) splitpair(kr[c].x, kr[c].y, h[c], l[c]);
            *(uint4*)(base + tid * QROW)      = make_uint4(h[0], h[1], h[2], h[3]);
            *(uint4*)(base + tid * QROW + 16) = make_uint4(h[4], h[5], h[6], h[7]);
            char* kl = base + KHI;
            *(uint4*)(kl + tid * QROW)      = make_uint4(l[0], l[1], l[2], l[3]);
            *(uint4*)(kl + tid * QROW + 16) = make_uint4(l[4], l[5], l[6], l[7]);
        } else if (tid < 192) {
            const int key = (tid - 64) >> 1;
            const int dh  = ((tid - 64) & 1) * 8;
            char* vh = base + 2 * KHI;
            char* vl = vh + VHI;
            #pragma unroll
            for (int d = 0; d < 8; d++) {
                uint32_t hb, lb;
                split1(vr[d], hb, lb);
                *(unsigned short*)(vh + (dh + d) * VROW + key * 2) = (unsigned short)hb;
                *(unsigned short*)(vl + (dh + d) * VROW + key * 2) = (unsigned short)lb;
            }
        }
    };

    stage_load(0);
    stage_store(0);
    __syncthreads();

    // ---- load persistent Q fragments ----
    uint32_t qh[MT][4], ql[MT][4];
    #pragma unroll
    for (int mt = 0; mt < MT; mt++) {
        const uint32_t ad = sb + (uint32_t)((w * QW + mt * 16) * QROW) + qoff;
        ldsm4(qh[mt][0], qh[mt][1], qh[mt][2], qh[mt][3], ad);
        ldsm4(ql[mt][0], ql[mt][1], ql[mt][2], ql[mt][3], ad + SEQ * QROW);
    }

    float l0[MT], l1[MT], oacc[MT][2][4];
    #pragma unroll
    for (int mt = 0; mt < MT; mt++) {
        l0[mt] = 0.f; l1[mt] = 0.f;
        #pragma unroll
        for (int nv = 0; nv < 2; nv++)
            #pragma unroll
            for (int e = 0; e < 4; e++) oacc[mt][nv][e] = 0.f;
    }

    for (int t = 0; t < NTILES; t++) {
        if (t + 1 < NTILES) stage_load(t + 1);   // LDG hidden under compute
        const uint32_t kb = sb + QB + (t & 1) * KVSTR;
        #pragma unroll
        for (int h32 = 0; h32 < 2; h32++) {
            uint32_t kh[4][2], kl[4][2];
            #pragma unroll
            for (int ntp = 0; ntp < 2; ntp++) {
                const uint32_t nb = kb + (uint32_t)((h32 * 32 + ntp * 16) * QROW) + qoff;
                ldsm4(kh[2*ntp][0], kh[2*ntp+1][0], kh[2*ntp][1], kh[2*ntp+1][1], nb);
                ldsm4(kl[2*ntp][0], kl[2*ntp+1][0], kl[2*ntp][1], kl[2*ntp+1][1], nb + KHI);
            }
            const uint32_t vb = kb + 2 * KHI;
            uint32_t bvh[2][2][2], bvl[2][2][2];
            #pragma unroll
            for (int kc = 0; kc < 2; kc++) {
                const uint32_t ad = vb + voffl + (uint32_t)(h32 * 64 + kc * 32);
                ldsm4(bvh[kc][0][0], bvh[kc][1][0], bvh[kc][0][1], bvh[kc][1][1], ad);
                ldsm4(bvl[kc][0][0], bvl[kc][1][0], bvl[kc][0][1], bvl[kc][1][1], ad + VHI);
            }
            #pragma unroll
            for (int mt = 0; mt < MT; mt++) {
                float s[4][4];
                #pragma unroll
                for (int nt = 0; nt < 4; nt++)
                    #pragma unroll
                    for (int e = 0; e < 4; e++) s[nt][e] = 0.f;
                #pragma unroll
                for (int nt = 0; nt < 4; nt++) {
                    mma_bf16(s[nt], qh[mt], kh[nt]);
                    mma_bf16(s[nt], qh[mt], kl[nt]);
                    mma_bf16(s[nt], ql[mt], kh[nt]);
                }
                float sl0 = 0.f, sl1 = 0.f;
                #pragma unroll
                for (int nt = 0; nt < 4; nt++) {
                    s[nt][0] = __expf(s[nt][0]);
                    s[nt][1] = __expf(s[nt][1]);
                    s[nt][2] = __expf(s[nt][2]);
                    s[nt][3] = __expf(s[nt][3]);
                    sl0 += s[nt][0] + s[nt][1];
                    sl1 += s[nt][2] + s[nt][3];
                }
                sl0 += __shfl_xor_sync(0xFFFFFFFFu, sl0, 1);
                sl0 += __shfl_xor_sync(0xFFFFFFFFu, sl0, 2);
                sl1 += __shfl_xor_sync(0xFFFFFFFFu, sl1, 1);
                sl1 += __shfl_xor_sync(0xFFFFFFFFu, sl1, 2);
                l0[mt] += sl0; l1[mt] += sl1;
                #pragma unroll
                for (int kc = 0; kc < 2; kc++) {
                    uint32_t ph[4], pl[4];
                    splitpair(s[2*kc][0],   s[2*kc][1],   ph[0], pl[0]);
                    splitpair(s[2*kc][2],   s[2*kc][3],   ph[1], pl[1]);
                    splitpair(s[2*kc+1][0], s[2*kc+1][1], ph[2], pl[2]);
                    splitpair(s[2*kc+1][2], s[2*kc+1][3], ph[3], pl[3]);
                    #pragma unroll
                    for (int nv = 0; nv < 2; nv++) {
                        mma_bf16(oacc[mt][nv], ph, bvh[kc][nv]);
                        mma_bf16(oacc[mt][nv], ph, bvl[kc][nv]);
                        mma_bf16(oacc[mt][nv], pl, bvh[kc][nv]);
                    }
                }
            }
        }
        if (t + 1 < NTILES) stage_store((t + 1) & 1);
        __syncthreads();
    }

    // ---- epilogue: normalize + split-store ----
    const int lr = lane >> 2, lc = lane & 3;
    #pragma unroll
    for (int mt = 0; mt < MT; mt++) {
        const float inv0 = 1.f / l0[mt];
        const float inv1 = 1.f / l1[mt];
        #pragma unroll
        for (int nv = 0; nv < 2; nv++) {
            const int q0 = w * QW + mt * 16 + lr;
            const int col = a * 16 + nv * 8 + lc * 2;
            uint32_t h, l;
            splitpair(oacc[mt][nv][0] * inv0, oacc[mt][nv][1] * inv0, h, l);
            const size_t off0 = rowof(q0) * 256 + col;
            *(uint32_t*)(oH + off0) = h;
            *(uint32_t*)(oL + off0) = l;
            splitpair(oacc[mt][nv][2] * inv1, oacc[mt][nv][3] * inv1, h, l);
            const size_t off1 = rowof(q0 + 8) * 256 + col;
            *(uint32_t*)(oH + off1) = h;
            *(uint32_t*)(oL + off1) = l;
        }
    }
}

// ---------------------------------------------------------------------------
extern "C" void kernel_launch(void* const* d_in, const int* in_sizes, int n_in,
                              void* d_out, int out_size)
{
    const float* x     = (const float*)d_in[0];
    const float* W1    = (const float*)d_in[1];
    const float* W2    = (const float*)d_in[2];
    const float* fc1_w = (const float*)d_in[3];
    const float* fc1_b = (const float*)d_in[4];
    const float* fc2_w = (const float*)d_in[5];
    const float* fc2_b = (const float*)d_in[6];
    float* out = (float*)d_out;

    bf16 *xhi, *xlo, *thi, *tlo, *pahi, *palo;
    bf16 *w1h, *w1l, *w2h, *w2l, *f2h, *f2l, *f1ah, *f1al, *w12h, *w12l;
    float *y1, *y2, *w12p, *b12;
    cudaGetSymbolAddress((void**)&xhi, g_xhi);   cudaGetSymbolAddress((void**)&xlo, g_xlo);
    cudaGetSymbolAddress((void**)&y1, g_y1);     cudaGetSymbolAddress((void**)&y2, g_y2);
    cudaGetSymbolAddress((void**)&thi, g_thi);   cudaGetSymbolAddress((void**)&tlo, g_tlo);
    cudaGetSymbolAddress((void**)&pahi, g_pahi); cudaGetSymbolAddress((void**)&palo, g_palo);
    cudaGetSymbolAddress((void**)&w1h, g_w1t_hi); cudaGetSymbolAddress((void**)&w1l, g_w1t_lo);
    cudaGetSymbolAddress((void**)&w2h, g_w2t_hi); cudaGetSymbolAddress((void**)&w2l, g_w2t_lo);
    cudaGetSymbolAddress((void**)&f2h, g_f2t_hi); cudaGetSymbolAddress((void**)&f2l, g_f2t_lo);
    cudaGetSymbolAddress((void**)&f1ah, g_f1a_hi); cudaGetSymbolAddress((void**)&f1al, g_f1a_lo);
    cudaGetSymbolAddress((void**)&w12p, g_w12p);
    cudaGetSymbolAddress((void**)&w12h, g_w12h); cudaGetSymbolAddress((void**)&w12l, g_w12l);
    cudaGetSymbolAddress((void**)&b12, g_b12);

    cudaFuncSetAttribute(gemm_mma<0>, cudaFuncAttributeMaxDynamicSharedMemorySize, SMEM_BYTES);
    cudaFuncSetAttribute(gemm_mma<1>, cudaFuncAttributeMaxDynamicSharedMemorySize, SMEM_BYTES);
    cudaFuncSetAttribute(gemm_mma<2>, cudaFuncAttributeMaxDynamicSharedMemorySize, SMEM_BYTES);

    // 0) conversions + b12
    conv_all<<<5664, 256>>>(x, xhi, xlo, W1, W2, fc1_w, fc2_w, fc1_b, fc2_b,
                            w1h, w1l, w2h, w2l, f2h, f2l, f1ah, f1al, b12);
    // 1) QKV1
    gemm_mma<0><<<dim3(768 / TN, ROWS / TM), 256, SMEM_BYTES>>>(
        xhi, xlo, w1h, w1l, y1, nullptr, nullptr, nullptr, 128, 768, 128);
    // 2) temporal attention (MMA flash)
    attn_mma<128, 1><<<dim3(PP, HD), 256>>>(y1, thi, tlo);
    // 3) QKV2
    gemm_mma<0><<<dim3(768 / TN, ROWS / TM), 256, SMEM_BYTES>>>(
        thi, tlo, w2h, w2l, y2, nullptr, nullptr, nullptr, 256, 768, 256);
    // 4) W12T = fc2_w^T @ fc1_w^T  (split-K=8; independent of attn chain)
    gemm_mma<2><<<dim3(2, 2, 8), 256, SMEM_BYTES>>>(
        f2h, f2l, f1ah, f1al, w12p, nullptr, nullptr, nullptr, 256, 256, 2048);
    // 5) point attention (MMA flash)   [launch index 5: ncu capture target]
    attn_mma<256, 0><<<dim3(NN, HD), 256>>>(y2, pahi, palo);
    // 6) reduce W12 partials + split
    w12_reduce_split<<<64, 256>>>(w12p, w12h, w12l);
    // 7) fused FC: out = pa @ W12 + b12
    gemm_mma<0><<<dim3(256 / TN, ROWS / TM), 256, SMEM_BYTES>>>(
        pahi, palo, w12h, w12l, out, nullptr, nullptr, b12, 256, 256, 256);
}

// round 15
// speedup vs baseline: 1.1513x; 1.1513x over previous
#include <cuda_runtime.h>
#include <cuda_bf16.h>
#include <cstdint>

typedef __nv_bfloat16 bf16;
typedef unsigned long long u64;

#define NN 128
#define PP 256
#define DD 128
#define HD 16
#define ROWS (NN*PP)      // 32768
#define HIDDEN 2048

// ---------------- scratch (device globals; no cudaMalloc allowed) ----------
__device__ bf16  g_xhi[(size_t)ROWS * DD],    g_xlo[(size_t)ROWS * DD];
__device__ float g_y1 [(size_t)ROWS * 768];
__device__ bf16  g_thi[(size_t)ROWS * 256],   g_tlo[(size_t)ROWS * 256];
__device__ float g_y2 [(size_t)ROWS * 768];
__device__ bf16  g_pahi[(size_t)ROWS * 256],  g_palo[(size_t)ROWS * 256];
// transposed split weights: Bt[n][k]
__device__ bf16  g_w1t_hi[768 * 128],   g_w1t_lo[768 * 128];
__device__ bf16  g_w2t_hi[768 * 256],   g_w2t_lo[768 * 256];
__device__ bf16  g_f2t_hi[256 * 2048],  g_f2t_lo[256 * 2048];   // fc2_w^T split
__device__ bf16  g_f1a_hi[256 * 2048],  g_f1a_lo[256 * 2048];   // fc1_w row-major split
// fused FC weight: W12T = fc2_w^T @ fc1_w^T (split-K partials, then split)
__device__ float g_w12p[8 * 256 * 256];
__device__ bf16  g_w12h[256 * 256],     g_w12l[256 * 256];
__device__ float g_b12[256];

// ---------------- helpers ---------------------------------------------------
__device__ __forceinline__ uint32_t smem_u32(const void* p) {
    uint32_t a;
    asm("{ .reg .u64 t; cvta.to.shared.u64 t, %1; cvt.u32.u64 %0, t; }"
        : "=r"(a) : "l"(p));
    return a;
}
__device__ __forceinline__ void cp16(uint32_t dst, const void* src) {
    asm volatile("cp.async.cg.shared.global [%0], [%1], 16;"
                 :: "r"(dst), "l"(src) : "memory");
}
__device__ __forceinline__ void mma_bf16(float* d, const uint32_t* a, const uint32_t* b) {
    asm volatile(
        "mma.sync.aligned.m16n8k16.row.col.f32.bf16.bf16.f32 "
        "{%0,%1,%2,%3}, {%4,%5,%6,%7}, {%8,%9}, {%0,%1,%2,%3};"
        : "+f"(d[0]), "+f"(d[1]), "+f"(d[2]), "+f"(d[3])
        : "r"(a[0]), "r"(a[1]), "r"(a[2]), "r"(a[3]), "r"(b[0]), "r"(b[1]));
}
__device__ __forceinline__ void ldsm4(uint32_t& r0, uint32_t& r1, uint32_t& r2,
                                      uint32_t& r3, uint32_t addr) {
    asm volatile("ldmatrix.sync.aligned.m8n8.x4.shared.b16 {%0,%1,%2,%3}, [%4];"
                 : "=r"(r0), "=r"(r1), "=r"(r2), "=r"(r3) : "r"(addr));
}
__device__ __forceinline__ void split1(float v, uint32_t& hb, uint32_t& lb) {
    bf16 h = __float2bfloat16(v);
    bf16 l = __float2bfloat16(v - __bfloat162float(h));
    hb = (uint32_t)__bfloat16_as_ushort(h);
    lb = (uint32_t)__bfloat16_as_ushort(l);
}
// pack two f32 into bf16x2 (even value -> low half)
__device__ __forceinline__ uint32_t packbf(float even, float odd) {
    uint32_t r;
    asm("cvt.rn.bf16x2.f32 %0, %1, %2;" : "=r"(r) : "f"(odd), "f"(even));
    return r;
}
// split pair (even,odd) into hi/lo bf16x2 regs
__device__ __forceinline__ void splitpair(float e, float o, uint32_t& h, uint32_t& l) {
    h = packbf(e, o);
    const float he = __uint_as_float(h << 16);
    const float ho = __uint_as_float(h & 0xffff0000u);
    l = packbf(e - he, o - ho);
}

// ---------------- split-bf16 mma.sync GEMM ---------------------------------
#define TM 128
#define TN 128
#define KC 32
#define ROWB 64
#define OPB (128 * ROWB)
#define STB (4 * OPB)
#define NSTG 3
#define SMEM_BYTES (NSTG * STB)      // 98304

template <int EPI>
__global__ __launch_bounds__(256, 2) void gemm_mma(
    const bf16* __restrict__ Ahi, const bf16* __restrict__ Alo,
    const bf16* __restrict__ Bhi, const bf16* __restrict__ Blo,
    float* __restrict__ C, bf16* __restrict__ Chi, bf16* __restrict__ Clo,
    const float* __restrict__ bias, int K, int ldc, int lda)
{
    extern __shared__ char smem[];
    const uint32_t sb = smem_u32(smem);
    const int tid = threadIdx.x, lane = tid & 31, wid = tid >> 5;
    const int wm = wid >> 2, wn = wid & 3;
    const int bn = blockIdx.x * TN, bm = blockIdx.y * TM;
    const int lr = lane >> 2, lc = lane & 3;
    const int koff = (EPI == 2) ? (int)blockIdx.z * K : 0;

    const int j  = lane >> 3;
    const int rr = ((j & 1) << 3) + (lane & 7);
    const int xr = (rr >> 1) & 3;
    const int cj = j >> 1;
    uint32_t loff[2];
    loff[0] = (uint32_t)(rr * ROWB + (((0 + cj) ^ xr) << 4));
    loff[1] = (uint32_t)(rr * ROWB + (((2 + cj) ^ xr) << 4));

    float acc[4][4][4];
    #pragma unroll
    for (int i = 0; i < 4; i++)
        #pragma unroll
        for (int jj = 0; jj < 4; jj++)
            #pragma unroll
            for (int e = 0; e < 4; e++) acc[i][jj][e] = 0.f;

    const int nc = K / KC;

    auto load_stage = [&](int c) {
        const int buf = c % NSTG;
        const bf16* gs[4] = {
            Ahi + (size_t)bm * lda + koff + c * KC,
            Alo + (size_t)bm * lda + koff + c * KC,
            Bhi + (size_t)bn * lda + koff + c * KC,
            Blo + (size_t)bn * lda + koff + c * KC };
        #pragma unroll
        for (int op = 0; op < 4; op++) {
            #pragma unroll
            for (int l = 0; l < 2; l++) {
                const int idx = tid + l * 256;
                const int r = idx >> 2, c8 = idx & 3;
                const uint32_t dst = sb + buf * STB + op * OPB +
                    (uint32_t)(r * ROWB + ((c8 ^ ((r >> 1) & 3)) << 4));
                cp16(dst, gs[op] + (size_t)r * lda + c8 * 8);
            }
        }
        asm volatile("cp.async.commit_group;" ::: "memory");
    };

    load_stage(0);
    if (nc > 1) load_stage(1);

    for (int c = 0; c < nc; c++) {
        if (c < nc - 1) {
            asm volatile("cp.async.wait_group 1;" ::: "memory");
        } else {
            asm volatile("cp.async.wait_group 0;" ::: "memory");
        }
        __syncthreads();
        if (c + 2 < nc) load_stage(c + 2);

        const uint32_t st = sb + (c % NSTG) * STB;
        const uint32_t aB = st + (uint32_t)(wm * 64 * ROWB);
        const uint32_t bB = st + 2 * OPB + (uint32_t)(wn * 32 * ROWB);

        #pragma unroll
        for (int k16 = 0; k16 < 2; k16++) {
            const uint32_t lo = loff[k16];
            uint32_t bh[4][2], bl[4][2];
            #pragma unroll
            for (int ntp = 0; ntp < 2; ntp++) {
                const uint32_t nb = bB + (uint32_t)(ntp * 16 * ROWB) + lo;
                ldsm4(bh[2*ntp][0], bh[2*ntp+1][0], bh[2*ntp][1], bh[2*ntp+1][1], nb);
                ldsm4(bl[2*ntp][0], bl[2*ntp+1][0], bl[2*ntp][1], bl[2*ntp+1][1], nb + OPB);
            }
            uint32_t ah[2][4], al[2][4];
            ldsm4(ah[0][0], ah[0][1], ah[0][2], ah[0][3], aB + lo);
            ldsm4(al[0][0], al[0][1], al[0][2], al[0][3], aB + OPB + lo);
            #pragma unroll
            for (int mt = 0; mt < 4; mt++) {
                const int cur = mt & 1, nxt = cur ^ 1;
                if (mt < 3) {
                    const uint32_t ab = aB + (uint32_t)((mt + 1) * 16 * ROWB) + lo;
                    ldsm4(ah[nxt][0], ah[nxt][1], ah[nxt][2], ah[nxt][3], ab);
                    ldsm4(al[nxt][0], al[nxt][1], al[nxt][2], al[nxt][3], ab + OPB);
                }
                #pragma unroll
                for (int nt = 0; nt < 4; nt++) {
                    mma_bf16(acc[mt][nt], ah[cur], bh[nt]);
                    mma_bf16(acc[mt][nt], ah[cur], bl[nt]);
                    mma_bf16(acc[mt][nt], al[cur], bh[nt]);
                }
            }
        }
    }

    const size_t zoff = (EPI == 2) ? (size_t)blockIdx.z * 65536 : 0;
    #pragma unroll
    for (int mt = 0; mt < 4; mt++) {
        #pragma unroll
        for (int nt = 0; nt < 4; nt++) {
            const int row = bm + wm * 64 + mt * 16 + lr;
            const int col = bn + wn * 32 + nt * 8 + lc * 2;
            float v0 = acc[mt][nt][0], v1 = acc[mt][nt][1];
            float v2 = acc[mt][nt][2], v3 = acc[mt][nt][3];
            if (EPI == 0 && bias) {
                const float b0 = __ldg(bias + col), b1 = __ldg(bias + col + 1);
                v0 += b0; v1 += b1; v2 += b0; v3 += b1;
            }
            if (EPI != 1) {
                *(float2*)(C + zoff + (size_t)row * ldc + col)       = make_float2(v0, v1);
                *(float2*)(C + zoff + (size_t)(row + 8) * ldc + col) = make_float2(v2, v3);
            } else {
                uint32_t h0, l0, h1, l1;
                splitpair(v0, v1, h0, l0);
                splitpair(v2, v3, h1, l1);
                *(uint32_t*)(Chi + (size_t)row * ldc + col)       = h0;
                *(uint32_t*)(Chi + (size_t)(row + 8) * ldc + col) = h1;
                *(uint32_t*)(Clo + (size_t)row * ldc + col)       = l0;
                *(uint32_t*)(Clo + (size_t)(row + 8) * ldc + col) = l1;
            }
        }
    }
}

// ---------------- fused conversion kernel (ONE launch) ---------------------
__global__ __launch_bounds__(256) void conv_all(
    const float* __restrict__ x, bf16* __restrict__ xhi, bf16* __restrict__ xlo,
    const float* __restrict__ W1, const float* __restrict__ W2,
    const float* __restrict__ fc1w, const float* __restrict__ fc2w,
    const float* __restrict__ fc1b, const float* __restrict__ fc2b,
    bf16* __restrict__ w1h, bf16* __restrict__ w1l,
    bf16* __restrict__ w2h, bf16* __restrict__ w2l,
    bf16* __restrict__ f2h, bf16* __restrict__ f2l,
    bf16* __restrict__ f1ah, bf16* __restrict__ f1al,
    float* __restrict__ b12)
{
    __shared__ float tile[32][33];
    const int tid = threadIdx.x;
    int b = blockIdx.x;

    if (b < 4096) {                       // x split
        const int i = b * 256 + tid;
        float4 v = ((const float4*)x)[i];
        uint32_t h0, l0, h1, l1;
        splitpair(v.x, v.y, h0, l0);
        splitpair(v.z, v.w, h1, l1);
        ((uint2*)xhi)[i] = make_uint2(h0, h1);
        ((uint2*)xlo)[i] = make_uint2(l0, l1);
        return;
    }
    b -= 4096;

    if (b >= 800 && b < 1312) {           // fc1_w elementwise split (512)
        const int i = (b - 800) * 256 + tid;
        float4 v = ((const float4*)fc1w)[i];
        uint32_t h0, l0, h1, l1;
        splitpair(v.x, v.y, h0, l0);
        splitpair(v.z, v.w, h1, l1);
        ((uint2*)f1ah)[i] = make_uint2(h0, h1);
        ((uint2*)f1al)[i] = make_uint2(l0, l1);
        return;
    }
    if (b >= 1312) {                      // b12 (256 blocks, one n each)
        const int n = b - 1312;
        float s = 0.f;
        for (int k = tid; k < HIDDEN; k += 256)
            s += fc1b[k] * fc2w[(size_t)k * 256 + n];
        float* red = &tile[0][0];
        red[tid] = s;
        __syncthreads();
        for (int w = 128; w > 0; w >>= 1) {
            if (tid < w) red[tid] += red[tid + w];
            __syncthreads();
        }
        if (tid == 0) b12[n] = red[0] + fc2b[n];
        return;
    }

    const float* B; bf16 *Th, *Tl;
    int K, N, n_off, out_ld, bx, by;
    if (b < 96) {                          // W1 transpose-split
        const int q = b / 32, r = b % 32;
        B = W1 + (size_t)q * 128 * 256; Th = w1h; Tl = w1l;
        K = 128; N = 256; n_off = q * 256; out_ld = 128;
        bx = r % 8; by = r / 8;
    } else if (b < 288) {                  // W2 transpose-split
        b -= 96;
        const int q = b / 64, r = b % 64;
        B = W2 + (size_t)q * 256 * 256; Th = w2h; Tl = w2l;
        K = 256; N = 256; n_off = q * 256; out_ld = 256;
        bx = r % 8; by = r / 8;
    } else {                               // fc2_w transpose-split (512)
        b -= 288;
        B = fc2w; Th = f2h; Tl = f2l;
        K = 2048; N = 256; n_off = 0; out_ld = 2048;
        bx = b % 8; by = b / 8;
    }

    const int n0 = bx * 32, k0 = by * 32;
    const int tx = tid & 31, ty = tid >> 5;
    #pragma unroll
    for (int i = 0; i < 4; i++) {
        const int r = ty + i * 8;
        tile[r][tx] = B[(size_t)(k0 + r) * N + n0 + tx];
    }
    __syncthreads();
    #pragma unroll
    for (int i = 0; i < 4; i++) {
        const int n = ty + i * 8;
        const float v = tile[tx][n];
        uint32_t hb, lb;
        split1(v, hb, lb);
        const size_t o = (size_t)(n_off + n0 + n) * out_ld + k0 + tx;
        Th[o] = __ushort_as_bfloat16((unsigned short)hb);
        Tl[o] = __ushort_as_bfloat16((unsigned short)lb);
    }
}

// ---------------- W12 partial reduce + split -------------------------------
__global__ __launch_bounds__(256) void w12_reduce_split(
    const float* __restrict__ w12p, bf16* __restrict__ w12h, bf16* __restrict__ w12l)
{
    const int i = blockIdx.x * 256 + threadIdx.x;
    float4 s = ((const float4*)w12p)[i];
    #pragma unroll
    for (int z = 1; z < 8; z++) {
        float4 p = ((const float4*)w12p)[z * 16384 + i];
        s.x += p.x; s.y += p.y; s.z += p.z; s.w += p.w;
    }
    uint32_t h0, l0, h1, l1;
    splitpair(s.x, s.y, h0, l0);
    splitpair(s.z, s.w, h1, l1);
    ((uint2*)w12h)[i] = make_uint2(h0, h1);
    ((uint2*)w12l)[i] = make_uint2(l0, l1);
}

// ---------------- MMA flash attention (no-max streaming softmax) -----------
// R13 structure (staging after compute, before barrier). V staged transposed
// with 2 threads/key; float4 global loads throughout staging.
template <int SEQ, int TEMP>
__global__ __launch_bounds__(256) void attn_mma(
    const float* __restrict__ y, bf16* __restrict__ oH, bf16* __restrict__ oL)
{
    constexpr int QW = SEQ / 8;
    constexpr int MT = QW / 16;
    constexpr int QROW = 48;
    constexpr int VROW = 144;
    constexpr int KHI = 64 * QROW;
    constexpr int VHI = 16 * VROW;
    constexpr int KVSTR = 2 * KHI + 2 * VHI;
    constexpr int QB = 2 * SEQ * QROW;
    constexpr int NTILES = SEQ / 64;

    __shared__ char sm[QB + 2 * KVSTR];

    const int bx = blockIdx.x, a = blockIdx.y;
    const int tid = threadIdx.x, lane = tid & 31, w = tid >> 5;
    const uint32_t sb = smem_u32(sm);

    const int j  = lane >> 3;
    const int rr = ((j & 1) << 3) + (lane & 7);
    const int cj = j >> 1;
    const uint32_t qoff = (uint32_t)(rr * QROW + cj * 16);
    const uint32_t voffl = (uint32_t)(rr * VROW + cj * 16);

    auto rowof = [&](int idx) -> size_t {
        return TEMP ? ((size_t)idx * 256 + bx) : ((size_t)bx * 256 + idx);
    };

    // ---- stage Q (once), float4 loads ----
    if (tid < SEQ) {
        const float* p = y + rowof(tid) * 768 + a * 16;
        float4 f0 = ((const float4*)p)[0];
        float4 f1 = ((const float4*)p)[1];
        float4 f2 = ((const float4*)p)[2];
        float4 f3 = ((const float4*)p)[3];
        uint32_t h[8], l[8];
        splitpair(f0.x, f0.y, h[0], l[0]); splitpair(f0.z, f0.w, h[1], l[1]);
        splitpair(f1.x, f1.y, h[2], l[2]); splitpair(f1.z, f1.w, h[3], l[3]);
        splitpair(f2.x, f2.y, h[4], l[4]); splitpair(f2.z, f2.w, h[5], l[5]);
        splitpair(f3.x, f3.y, h[6], l[6]); splitpair(f3.z, f3.w, h[7], l[7]);
        *(uint4*)(sm + tid * QROW)      = make_uint4(h[0], h[1], h[2], h[3]);
        *(uint4*)(sm + tid * QROW + 16) = make_uint4(h[4], h[5], h[6], h[7]);
        char* ql = sm + SEQ * QROW;
        *(uint4*)(ql + tid * QROW)      = make_uint4(l[0], l[1], l[2], l[3]);
        *(uint4*)(ql + tid * QROW + 16) = make_uint4(l[4], l[5], l[6], l[7]);
    }

    auto stage_kv = [&](int kt, int buf) {
        char* base = sm + QB + buf * KVSTR;
        if (tid < 64) {                    // K row tid, float4 loads
            const float* p = y + rowof(kt * 64 + tid) * 768 + a * 16 + 256;
            float4 f0 = ((const float4*)p)[0];
            float4 f1 = ((const float4*)p)[1];
            float4 f2 = ((const float4*)p)[2];
            float4 f3 = ((const float4*)p)[3];
            uint32_t h[8], l[8];
            splitpair(f0.x, f0.y, h[0], l[0]); splitpair(f0.z, f0.w, h[1], l[1]);
            splitpair(f1.x, f1.y, h[2], l[2]); splitpair(f1.z, f1.w, h[3], l[3]);
            splitpair(f2.x, f2.y, h[4], l[4]); splitpair(f2.z, f2.w, h[5], l[5]);
            splitpair(f3.x, f3.y, h[6], l[6]); splitpair(f3.z, f3.w, h[7], l[7]);
            *(uint4*)(base + tid * QROW)      = make_uint4(h[0], h[1], h[2], h[3]);
            *(uint4*)(base + tid * QROW + 16) = make_uint4(h[4], h[5], h[6], h[7]);
            char* kl = base + KHI;
            *(uint4*)(kl + tid * QROW)      = make_uint4(l[0], l[1], l[2], l[3]);
            *(uint4*)(kl + tid * QROW + 16) = make_uint4(l[4], l[5], l[6], l[7]);
        } else if (tid < 192) {            // V: 2 threads per key, float4 loads
            const int key = (tid - 64) >> 1;
            const int dh  = ((tid - 64) & 1) * 8;
            const float* p = y + rowof(kt * 64 + key) * 768 + a * 16 + 512 + dh;
            float4 f0 = ((const float4*)p)[0];
            float4 f1 = ((const float4*)p)[1];
            float vv[8] = {f0.x, f0.y, f0.z, f0.w, f1.x, f1.y, f1.z, f1.w};
            char* vh = base + 2 * KHI;
            char* vl = vh + VHI;
            #pragma unroll
            for (int d = 0; d < 8; d++) {
                uint32_t hb, lb;
                split1(vv[d], hb, lb);
                *(unsigned short*)(vh + (dh + d) * VROW + key * 2) = (unsigned short)hb;
                *(unsigned short*)(vl + (dh + d) * VROW + key * 2) = (unsigned short)lb;
            }
        }
    };

    stage_kv(0, 0);
    __syncthreads();

    // ---- load persistent Q fragments ----
    uint32_t qh[MT][4], ql[MT][4];
    #pragma unroll
    for (int mt = 0; mt < MT; mt++) {
        const uint32_t ad = sb + (uint32_t)((w * QW + mt * 16) * QROW) + qoff;
        ldsm4(qh[mt][0], qh[mt][1], qh[mt][2], qh[mt][3], ad);
        ldsm4(ql[mt][0], ql[mt][1], ql[mt][2], ql[mt][3], ad + SEQ * QROW);
    }

    float l0[MT], l1[MT], oacc[MT][2][4];
    #pragma unroll
    for (int mt = 0; mt < MT; mt++) {
        l0[mt] = 0.f; l1[mt] = 0.f;
        #pragma unroll
        for (int nv = 0; nv < 2; nv++)
            #pragma unroll
            for (int e = 0; e < 4; e++) oacc[mt][nv][e] = 0.f;
    }

    for (int t = 0; t < NTILES; t++) {
        const uint32_t kb = sb + QB + (t & 1) * KVSTR;
        #pragma unroll
        for (int h32 = 0; h32 < 2; h32++) {
            uint32_t kh[4][2], kl[4][2];
            #pragma unroll
            for (int ntp = 0; ntp < 2; ntp++) {
                const uint32_t nb = kb + (uint32_t)((h32 * 32 + ntp * 16) * QROW) + qoff;
                ldsm4(kh[2*ntp][0], kh[2*ntp+1][0], kh[2*ntp][1], kh[2*ntp+1][1], nb);
                ldsm4(kl[2*ntp][0], kl[2*ntp+1][0], kl[2*ntp][1], kl[2*ntp+1][1], nb + KHI);
            }
            const uint32_t vb = kb + 2 * KHI;
            uint32_t bvh[2][2][2], bvl[2][2][2];
            #pragma unroll
            for (int kc = 0; kc < 2; kc++) {
                const uint32_t ad = vb + voffl + (uint32_t)(h32 * 64 + kc * 32);
                ldsm4(bvh[kc][0][0], bvh[kc][1][0], bvh[kc][0][1], bvh[kc][1][1], ad);
                ldsm4(bvl[kc][0][0], bvl[kc][1][0], bvl[kc][0][1], bvl[kc][1][1], ad + VHI);
            }
            #pragma unroll
            for (int mt = 0; mt < MT; mt++) {
                float s[4][4];
                #pragma unroll
                for (int nt = 0; nt < 4; nt++)
                    #pragma unroll
                    for (int e = 0; e < 4; e++) s[nt][e] = 0.f;
                #pragma unroll
                for (int nt = 0; nt < 4; nt++) {
                    mma_bf16(s[nt], qh[mt], kh[nt]);
                    mma_bf16(s[nt], qh[mt], kl[nt]);
                    mma_bf16(s[nt], ql[mt], kh[nt]);
                }
                float sl0 = 0.f, sl1 = 0.f;
                #pragma unroll
                for (int nt = 0; nt < 4; nt++) {
                    s[nt][0] = __expf(s[nt][0]);
                    s[nt][1] = __expf(s[nt][1]);
                    s[nt][2] = __expf(s[nt][2]);
                    s[nt][3] = __expf(s[nt][3]);
                    sl0 += s[nt][0] + s[nt][1];
                    sl1 += s[nt][2] + s[nt][3];
                }
                sl0 += __shfl_xor_sync(0xFFFFFFFFu, sl0, 1);
                sl0 += __shfl_xor_sync(0xFFFFFFFFu, sl0, 2);
                sl1 += __shfl_xor_sync(0xFFFFFFFFu, sl1, 1);
                sl1 += __shfl_xor_sync(0xFFFFFFFFu, sl1, 2);
                l0[mt] += sl0; l1[mt] += sl1;
                #pragma unroll
                for (int kc = 0; kc < 2; kc++) {
                    uint32_t ph[4], pl[4];
                    splitpair(s[2*kc][0],   s[2*kc][1],   ph[0], pl[0]);
                    splitpair(s[2*kc][2],   s[2*kc][3],   ph[1], pl[1]);
                    splitpair(s[2*kc+1][0], s[2*kc+1][1], ph[2], pl[2]);
                    splitpair(s[2*kc+1][2], s[2*kc+1][3], ph[3], pl[3]);
                    #pragma unroll
                    for (int nv = 0; nv < 2; nv++) {
                        mma_bf16(oacc[mt][nv], ph, bvh[kc][nv]);
                        mma_bf16(oacc[mt][nv], ph, bvl[kc][nv]);
                        mma_bf16(oacc[mt][nv], pl, bvh[kc][nv]);
                    }
                }
            }
        }
        if (t + 1 < NTILES) stage_kv(t + 1, (t + 1) & 1);
        __syncthreads();
    }

    // ---- epilogue: normalize + split-store ----
    const int lr = lane >> 2, lc = lane & 3;
    #pragma unroll
    for (int mt = 0; mt < MT; mt++) {
        const float inv0 = 1.f / l0[mt];
        const float inv1 = 1.f / l1[mt];
        #pragma unroll
        for (int nv = 0; nv < 2; nv++) {
            const int q0 = w * QW + mt * 16 + lr;
            const int col = a * 16 + nv * 8 + lc * 2;
            uint32_t h, l;
            splitpair(oacc[mt][nv][0] * inv0, oacc[mt][nv][1] * inv0, h, l);
            const size_t off0 = rowof(q0) * 256 + col;
            *(uint32_t*)(oH + off0) = h;
            *(uint32_t*)(oL + off0) = l;
            splitpair(oacc[mt][nv][2] * inv1, oacc[mt][nv][3] * inv1, h, l);
            const size_t off1 = rowof(q0 + 8) * 256 + col;
            *(uint32_t*)(oH + off1) = h;
            *(uint32_t*)(oL + off1) = l;
        }
    }
}

// ---------------------------------------------------------------------------
extern "C" void kernel_launch(void* const* d_in, const int* in_sizes, int n_in,
                              void* d_out, int out_size)
{
    const float* x     = (const float*)d_in[0];
    const float* W1    = (const float*)d_in[1];
    const float* W2    = (const float*)d_in[2];
    const float* fc1_w = (const float*)d_in[3];
    const float* fc1_b = (const float*)d_in[4];
    const float* fc2_w = (const float*)d_in[5];
    const float* fc2_b = (const float*)d_in[6];
    float* out = (float*)d_out;

    bf16 *xhi, *xlo, *thi, *tlo, *pahi, *palo;
    bf16 *w1h, *w1l, *w2h, *w2l, *f2h, *f2l, *f1ah, *f1al, *w12h, *w12l;
    float *y1, *y2, *w12p, *b12;
    cudaGetSymbolAddress((void**)&xhi, g_xhi);   cudaGetSymbolAddress((void**)&xlo, g_xlo);
    cudaGetSymbolAddress((void**)&y1, g_y1);     cudaGetSymbolAddress((void**)&y2, g_y2);
    cudaGetSymbolAddress((void**)&thi, g_thi);   cudaGetSymbolAddress((void**)&tlo, g_tlo);
    cudaGetSymbolAddress((void**)&pahi, g_pahi); cudaGetSymbolAddress((void**)&palo, g_palo);
    cudaGetSymbolAddress((void**)&w1h, g_w1t_hi); cudaGetSymbolAddress((void**)&w1l, g_w1t_lo);
    cudaGetSymbolAddress((void**)&w2h, g_w2t_hi); cudaGetSymbolAddress((void**)&w2l, g_w2t_lo);
    cudaGetSymbolAddress((void**)&f2h, g_f2t_hi); cudaGetSymbolAddress((void**)&f2l, g_f2t_lo);
    cudaGetSymbolAddress((void**)&f1ah, g_f1a_hi); cudaGetSymbolAddress((void**)&f1al, g_f1a_lo);
    cudaGetSymbolAddress((void**)&w12p, g_w12p);
    cudaGetSymbolAddress((void**)&w12h, g_w12h); cudaGetSymbolAddress((void**)&w12l, g_w12l);
    cudaGetSymbolAddress((void**)&b12, g_b12);

    cudaFuncSetAttribute(gemm_mma<0>, cudaFuncAttributeMaxDynamicSharedMemorySize, SMEM_BYTES);
    cudaFuncSetAttribute(gemm_mma<1>, cudaFuncAttributeMaxDynamicSharedMemorySize, SMEM_BYTES);
    cudaFuncSetAttribute(gemm_mma<2>, cudaFuncAttributeMaxDynamicSharedMemorySize, SMEM_BYTES);

    // 0) conversions + b12
    conv_all<<<5664, 256>>>(x, xhi, xlo, W1, W2, fc1_w, fc2_w, fc1_b, fc2_b,
                            w1h, w1l, w2h, w2l, f2h, f2l, f1ah, f1al, b12);
    // 1) W12T = fc2_w^T @ fc1_w^T  (split-K=8 partials)
    gemm_mma<2><<<dim3(2, 2, 8), 256, SMEM_BYTES>>>(
        f2h, f2l, f1ah, f1al, w12p, nullptr, nullptr, nullptr, 256, 256, 2048);
    // 2) reduce partials + split
    w12_reduce_split<<<64, 256>>>(w12p, w12h, w12l);
    // 3) QKV1
    gemm_mma<0><<<dim3(768 / TN, ROWS / TM), 256, SMEM_BYTES>>>(
        xhi, xlo, w1h, w1l, y1, nullptr, nullptr, nullptr, 128, 768, 128);
    // 4) temporal attention (MMA flash)
    attn_mma<128, 1><<<dim3(PP, HD), 256>>>(y1, thi, tlo);
    // 5) QKV2   [launch index 5: ncu capture target]
    gemm_mma<0><<<dim3(768 / TN, ROWS / TM), 256, SMEM_BYTES>>>(
        thi, tlo, w2h, w2l, y2, nullptr, nullptr, nullptr, 256, 768, 256);
    // 6) point attention (MMA flash)
    attn_mma<256, 0><<<dim3(NN, HD), 256>>>(y2, pahi, palo);
    // 7) fused FC: out = pa @ W12 + b12
    gemm_mma<0><<<dim3(256 / TN, ROWS / TM), 256, SMEM_BYTES>>>(
        pahi, palo, w12h, w12l, out, nullptr, nullptr, b12, 256, 256, 256);
}